// round 14
// baseline (speedup 1.0000x reference)
#include <cuda_runtime.h>

// ForwardKinematicsLayer — SMPL 24-joint FK, batch = 262144.
//
// Inputs (metadata order):
//   d_in[0] local_rots : f32 [B, 24, 3, 3]   (B*216 elements)
//   d_in[1] root_pos   : f32 [B, 3]
//   d_in[2] offsets    : f32 [24, 3]
// Output:
//   d_out[0 .. B*72)        global_pos : f32 [B, 24, 3]
//   d_out[B*72 .. B*288)    global_rots: f32 [B, 24, 3, 3]
//
// R13 design = R11 winner (TPB=128, ITEMS=32, 5 CTAs/SM, 84.9us) with the
// FK chain ROW-DECOMPOSED across 3 threads per item:
//   row i of G[j] = G[p][i,:] @ L[j]  and  P[j][i] = P[p][i] + G[p][i,:]@off
// depend only on row i of the parent -> three fully independent row-chains,
// no cross-thread traffic. 4 threads/item (3 rows + 1 idle) keeps each
// item's group inside one warp, so converged-warp program order makes the
// in-place L[j] -> G[j] smem update race-free. Compute window shrinks ~3x
// (the R12 experiment proved this serial window is what drains DRAM).

#define NJ     24
#define TPB    128
#define ITEMS  32
#define RPAD   217                  // 216 rot floats + 1 pad (odd word stride)
#define PPAD   73                   // 72 pos floats + 1 pad (odd word stride)

static __device__ __forceinline__ int par_of(int j) {
    constexpr int kPar[NJ] = {-1, 0, 0, 0, 1, 2, 3, 4, 5, 6, 7, 8,
                               9, 9, 9, 12, 13, 14, 16, 17, 18, 19, 20, 21};
    return kPar[j];
}

__global__ void __launch_bounds__(TPB, 5)
fk_kernel(const float* __restrict__ lrots,   // [B,24,3,3]
          const float* __restrict__ rootp,   // [B,3]
          const float* __restrict__ offs,    // [24,3]
          float* __restrict__ out,           // [B*72 pos | B*216 rot]
          int batch)
{
    extern __shared__ float sm[];            // rot: ITEMS*RPAD | pos: ITEMS*PPAD
    float* rsm = sm;
    float* psm = sm + ITEMS * RPAD;
    __shared__ float soffs[NJ * 3];

    const int tid = threadIdx.x;
    const long long base_item = (long long)blockIdx.x * ITEMS;

    if (tid < NJ * 3) soffs[tid] = offs[tid];   // 72 < TPB=128: single fill OK

    const float* in_rot  = lrots + base_item * 216;
    float*       out_pos = out;
    float*       out_rot = out + (long long)batch * 72;

    // ------- Phase 1: coalesced gmem -> smem (local rots + root pos) -------
    // 32*216/128 = 54 fully-unrolled iterations => deep LDG MLP per warp.
#pragma unroll
    for (int k = 0; k < (ITEMS * 216) / TPB; ++k) {
        int idx  = k * TPB + tid;
        int item = idx / 216;
        int e    = idx - item * 216;
        rsm[item * RPAD + e] = in_rot[idx];
    }
    {   // root positions -> pos smem rows [item*PPAD + 0..2]  (96 words < TPB)
        const float* rp = rootp + base_item * 3;
        if (tid < ITEMS * 3) {
            int item = tid / 3;
            int c    = tid - item * 3;
            psm[item * PPAD + c] = rp[tid];
        }
    }
    __syncthreads();

    // ------- Phase 2: FK chain, row-parallel: 4 threads/item, rows 0..2 ----
    {
        const int g = tid >> 2;              // item within tile (0..31)
        const int r = tid & 3;               // row (0..2 active, 3 idle)

        if (r < 3) {
            float* my = rsm + g * RPAD;      // this item's 24 rot slots
            float* mp = psm + g * PPAD;      // this item's 24 pos slots

            float Gr[NJ][3];                 // row r of each G[j]; ~1 parent live
            float Pr[NJ];                    // component r of each position

#pragma unroll
            for (int c = 0; c < 3; ++c) Gr[0][c] = my[r * 3 + c]; // G0 == L0
            Pr[0] = mp[r];                                        // root pos

#pragma unroll
            for (int j = 1; j < NJ; ++j) {
                const int p = par_of(j);

                float L[9];                  // whole L[j] (broadcast LDS)
#pragma unroll
                for (int c = 0; c < 9; ++c) L[c] = my[j * 9 + c];

                // position component r
                Pr[j] = Pr[p]
                      + Gr[p][0] * soffs[j * 3 + 0]
                      + Gr[p][1] * soffs[j * 3 + 1]
                      + Gr[p][2] * soffs[j * 3 + 2];
                mp[j * 3 + r] = Pr[j];

                // row r of G[j] = Gr[p] @ L[j], written in place over L[j]
#pragma unroll
                for (int c = 0; c < 3; ++c) {
                    float v = Gr[p][0] * L[0 * 3 + c]
                            + Gr[p][1] * L[1 * 3 + c]
                            + Gr[p][2] * L[2 * 3 + c];
                    Gr[j][c] = v;
                    my[j * 9 + r * 3 + c] = v;
                }
            }
        }
    }
    __syncthreads();

    // ------- Phase 3: coalesced smem -> gmem (global rots, then pos) -------
    {
        const long long rot_base = base_item * 216;
#pragma unroll
        for (int k = 0; k < (ITEMS * 216) / TPB; ++k) {   // 54 iterations
            int idx  = k * TPB + tid;
            int item = idx / 216;
            int e    = idx - item * 216;
            out_rot[rot_base + idx] = rsm[item * RPAD + e];
        }
        const long long pos_base = base_item * 72;
#pragma unroll
        for (int k = 0; k < (ITEMS * 72) / TPB; ++k) {    // 18 iterations
            int idx  = k * TPB + tid;
            int item = idx / 72;
            int e    = idx - item * 72;
            out_pos[pos_base + idx] = psm[item * PPAD + e];
        }
    }
}

extern "C" void kernel_launch(void* const* d_in, const int* in_sizes, int n_in,
                              void* d_out, int out_size)
{
    const float* lrots = (const float*)d_in[0];
    const float* rootp = (const float*)d_in[1];
    const float* offs  = (const float*)d_in[2];
    float*       out   = (float*)d_out;

    const int batch = in_sizes[0] / 216;                 // 262144
    const int grid  = batch / ITEMS;                     // 8192 blocks
    const int smem  = (ITEMS * RPAD + ITEMS * PPAD) * (int)sizeof(float); // 37,120 B

    cudaFuncSetAttribute(fk_kernel,
                         cudaFuncAttributeMaxDynamicSharedMemorySize, smem);

    fk_kernel<<<grid, TPB, smem>>>(lrots, rootp, offs, out, batch);
}

// round 15
// speedup vs baseline: 1.2449x; 1.2449x over previous
#include <cuda_runtime.h>

// ForwardKinematicsLayer — SMPL 24-joint FK, batch = 262144.
//
// Inputs (metadata order):
//   d_in[0] local_rots : f32 [B, 24, 3, 3]   (B*216 elements)
//   d_in[1] root_pos   : f32 [B, 3]
//   d_in[2] offsets    : f32 [24, 3]
// Output:
//   d_out[0 .. B*72)        global_pos : f32 [B, 24, 3]
//   d_out[B*72 .. B*288)    global_rots: f32 [B, 24, 3, 3]
//
// R14 design = R11 winner (TPB=128, ITEMS=32, 5 CTAs/SM, one thread per
// item, odd smem strides 217/73) + two targeted changes:
//  1. FK chain PREFETCHES L[j+1] and off[j+1] into registers one joint
//     ahead -> the 29-cyc LDS is off the serial path; per-joint cost drops
//     toward the pure-FFMA floor. (R13/R12 showed this serial window is
//     what drains DRAM; R13 also showed restructuring parallelism doesn't
//     shorten it — latency does.)
//  2. Streaming cache hints: __ldcs on input reads, __stcs on output
//     stores (zero-reuse kernel; keep L2 evict-first).

#define NJ     24
#define TPB    128
#define ITEMS  32
#define RPAD   217                  // 216 rot floats + 1 pad (odd word stride)
#define PPAD   73                   // 72 pos floats + 1 pad (odd word stride)

static __device__ __forceinline__ int par_of(int j) {
    constexpr int kPar[NJ] = {-1, 0, 0, 0, 1, 2, 3, 4, 5, 6, 7, 8,
                               9, 9, 9, 12, 13, 14, 16, 17, 18, 19, 20, 21};
    return kPar[j];
}

__global__ void __launch_bounds__(TPB, 5)
fk_kernel(const float* __restrict__ lrots,   // [B,24,3,3]
          const float* __restrict__ rootp,   // [B,3]
          const float* __restrict__ offs,    // [24,3]
          float* __restrict__ out,           // [B*72 pos | B*216 rot]
          int batch)
{
    extern __shared__ float sm[];            // rot: ITEMS*RPAD | pos: ITEMS*PPAD
    float* rsm = sm;
    float* psm = sm + ITEMS * RPAD;
    __shared__ float soffs[NJ * 3];

    const int tid = threadIdx.x;
    const long long base_item = (long long)blockIdx.x * ITEMS;

    if (tid < NJ * 3) soffs[tid] = offs[tid];   // 72 < TPB=128: single fill OK

    const float* in_rot  = lrots + base_item * 216;
    float*       out_pos = out;
    float*       out_rot = out + (long long)batch * 72;

    // ------- Phase 1: coalesced gmem -> smem (local rots + root pos) -------
    // 32*216/128 = 54 fully-unrolled iterations => deep LDG MLP per warp.
#pragma unroll
    for (int k = 0; k < (ITEMS * 216) / TPB; ++k) {
        int idx  = k * TPB + tid;
        int item = idx / 216;
        int e    = idx - item * 216;
        rsm[item * RPAD + e] = __ldcs(&in_rot[idx]);
    }
    {   // root positions -> pos smem rows [item*PPAD + 0..2]  (96 words < TPB)
        const float* rp = rootp + base_item * 3;
        if (tid < ITEMS * 3) {
            int item = tid / 3;
            int c    = tid - item * 3;
            psm[item * PPAD + c] = __ldcs(&rp[tid]);
        }
    }
    __syncthreads();

    // ------- Phase 2: FK chain, threads 0..31, L[j+1] prefetched -----------
    if (tid < ITEMS) {
        float* my = rsm + tid * RPAD;        // this item's 24 rot slots
        float* mp = psm + tid * PPAD;        // this item's 24 pos slots

        float G[NJ][9];                      // SSA'd by full unroll; ~3 live
        float P[NJ][3];

#pragma unroll
        for (int c = 0; c < 9; ++c) G[0][c] = my[c];    // joint 0: G == L
#pragma unroll
        for (int c = 0; c < 3; ++c) P[0][c] = mp[c];    // root pos (staged)

        // Prefetch joint 1's local rot + offset into registers.
        float Lb[9], ob0, ob1, ob2;
#pragma unroll
        for (int c = 0; c < 9; ++c) Lb[c] = my[9 + c];
        ob0 = soffs[3]; ob1 = soffs[4]; ob2 = soffs[5];

#pragma unroll
        for (int j = 1; j < NJ; ++j) {
            const int p = par_of(j);

            // Consume the prefetched operands for joint j.
            float L[9];
#pragma unroll
            for (int c = 0; c < 9; ++c) L[c] = Lb[c];
            const float o0 = ob0, o1 = ob1, o2 = ob2;

            // Issue next joint's prefetch BEFORE the FMA chain (covers LDS).
            if (j + 1 < NJ) {
#pragma unroll
                for (int c = 0; c < 9; ++c) Lb[c] = my[(j + 1) * 9 + c];
                ob0 = soffs[(j + 1) * 3 + 0];
                ob1 = soffs[(j + 1) * 3 + 1];
                ob2 = soffs[(j + 1) * 3 + 2];
            }

#pragma unroll
            for (int i = 0; i < 3; ++i) {
                P[j][i] = P[p][i]
                        + G[p][i * 3 + 0] * o0
                        + G[p][i * 3 + 1] * o1
                        + G[p][i * 3 + 2] * o2;
                mp[j * 3 + i] = P[j][i];     // stage pos immediately
            }
#pragma unroll
            for (int i = 0; i < 3; ++i) {
#pragma unroll
                for (int c = 0; c < 3; ++c) {
                    float g = G[p][i * 3 + 0] * L[0 * 3 + c]
                            + G[p][i * 3 + 1] * L[1 * 3 + c]
                            + G[p][i * 3 + 2] * L[2 * 3 + c];
                    G[j][i * 3 + c] = g;
                    my[j * 9 + i * 3 + c] = g;   // stage global rot in place
                }
            }
        }
    }
    __syncthreads();

    // ------- Phase 3: coalesced smem -> gmem (global rots, then pos) -------
    {
        const long long rot_base = base_item * 216;
#pragma unroll
        for (int k = 0; k < (ITEMS * 216) / TPB; ++k) {   // 54 iterations
            int idx  = k * TPB + tid;
            int item = idx / 216;
            int e    = idx - item * 216;
            __stcs(&out_rot[rot_base + idx], rsm[item * RPAD + e]);
        }
        const long long pos_base = base_item * 72;
#pragma unroll
        for (int k = 0; k < (ITEMS * 72) / TPB; ++k) {    // 18 iterations
            int idx  = k * TPB + tid;
            int item = idx / 72;
            int e    = idx - item * 72;
            __stcs(&out_pos[pos_base + idx], psm[item * PPAD + e]);
        }
    }
}

extern "C" void kernel_launch(void* const* d_in, const int* in_sizes, int n_in,
                              void* d_out, int out_size)
{
    const float* lrots = (const float*)d_in[0];
    const float* rootp = (const float*)d_in[1];
    const float* offs  = (const float*)d_in[2];
    float*       out   = (float*)d_out;

    const int batch = in_sizes[0] / 216;                 // 262144
    const int grid  = batch / ITEMS;                     // 8192 blocks
    const int smem  = (ITEMS * RPAD + ITEMS * PPAD) * (int)sizeof(float); // 37,120 B

    cudaFuncSetAttribute(fk_kernel,
                         cudaFuncAttributeMaxDynamicSharedMemorySize, smem);

    fk_kernel<<<grid, TPB, smem>>>(lrots, rootp, offs, out, batch);
}